// round 5
// baseline (speedup 1.0000x reference)
#include <cuda_runtime.h>
#include <cstdint>

#define OUT_ELEMS   25165824L   // 128*256*768
#define PROBS_ELEMS 50331648L   // 12*256*128*128

// Scratch (allocation-free rule: device globals)
__device__ float g_q[25165824];
__device__ float g_k[25165824];
__device__ float g_v[25165824];
__device__ float g_ctx[25165824];
__device__ float g_xr[25165824];
__device__ float g_wr[4][589824];   // rounded Wq,Wk,Wv,Wo; [0..2] = fused [2304,768]

// ---------------------------------------------------------------------------
// Helpers
// ---------------------------------------------------------------------------
__device__ __forceinline__ uint32_t smem_u32(const void* p) {
    uint32_t a;
    asm("{ .reg .u64 t; cvta.to.shared.u64 t, %1; cvt.u32.u64 %0, t; }" : "=r"(a) : "l"(p));
    return a;
}
__device__ __forceinline__ float tf32r(float x) {
    float y; asm("cvt.rna.tf32.f32 %0, %1;" : "=f"(y) : "f"(x)); return y;
}
__device__ __forceinline__ void cp16(uint32_t s, const void* g) {
    asm volatile("cp.async.cg.shared.global [%0], [%1], 16;"
        :: "r"(s), "l"((unsigned long long)__cvta_generic_to_global(g)) : "memory");
}
__device__ __forceinline__ void mma1688(float (&d)[4], const uint32_t (&a)[4], const uint32_t (&b)[2]) {
    asm volatile(
        "mma.sync.aligned.m16n8k8.row.col.f32.tf32.tf32.f32 "
        "{%0,%1,%2,%3}, {%4,%5,%6,%7}, {%8,%9}, {%0,%1,%2,%3};"
        : "+f"(d[0]), "+f"(d[1]), "+f"(d[2]), "+f"(d[3])
        : "r"(a[0]), "r"(a[1]), "r"(a[2]), "r"(a[3]), "r"(b[0]), "r"(b[1]));
}

// ---------------------------------------------------------------------------
// tf32 mma.sync NT-GEMM, 3-stage cp.async, k-permuted LDS.128 fragments.
// A [M,768] row-major; B fused [nparts*768, 768] row-major; N_out = 768/part.
// part = blockIdx.x/6 selects bias/output; scale applied for part 0 only.
// BM=BN=128, BK=32, 256 thr, warp 4m x 2n, warp tile 32x64.
//
// k-permutation: for mma-step t (t=0..3 within a 32-k tile), slot tg holds
// k = 8*tg + 2t and slot tg+4 holds k = 8*tg + 2t + 1. A and B use the same
// permutation, so the k-sum is unchanged. Each thread's operands for the
// whole 32-k tile are 8 contiguous floats per row -> 2x LDS.128.
// ---------------------------------------------------------------------------
#define NS 3
#define LDA      36
#define A_FLOATS (128 * LDA)            // 4608
#define STAGE_F  (2 * A_FLOATS)         // 9216 floats (A+B)
#define GEMM_SMEM (NS * STAGE_F * 4)    // 110592 bytes
#define NT 24                           // K=768/32

__device__ __forceinline__ void load_stage(
    float* stg, const float* Ab, const float* Bb, int k0, int tid)
{
#pragma unroll
    for (int i = 0; i < 4; i++) {
        int q  = tid + i * 256;     // 0..1023
        int r  = q >> 3;            // row 0..127
        int cc = q & 7;             // 16B chunk
        cp16(smem_u32(stg + r * LDA + cc * 4),            Ab + (long)r * 768 + k0 + cc * 4);
        cp16(smem_u32(stg + A_FLOATS + r * LDA + cc * 4), Bb + (long)r * 768 + k0 + cc * 4);
    }
    asm volatile("cp.async.commit_group;" ::: "memory");
}

__global__ __launch_bounds__(256, 2) void gemm_mma(
    const float* __restrict__ A, const float* __restrict__ B,
    const float* __restrict__ bias0, const float* __restrict__ bias1,
    const float* __restrict__ bias2,
    float* __restrict__ C0, float* __restrict__ C1, float* __restrict__ C2,
    float s0, int do_round)
{
    extern __shared__ float sm[];

    const int tid  = threadIdx.x;
    const int wid  = tid >> 5;
    const int lane = tid & 31;
    const int g    = lane >> 2;
    const int tg   = lane & 3;
    const int wm   = wid >> 1;
    const int wn   = wid & 1;
    const long bm  = (long)blockIdx.y * 128;
    const int part = blockIdx.x / 6;
    const int bn   = (blockIdx.x % 6) * 128;     // col within 768-wide output

    const float* bias = (part == 0) ? bias0 : (part == 1) ? bias1 : bias2;
    float* C          = (part == 0) ? C0    : (part == 1) ? C1    : C2;
    const float scale = (part == 0) ? s0 : 1.0f;

    const float* Ab = A + bm * 768;
    const float* Bb = B + (long)blockIdx.x * 128 * 768;

    float acc[2][8][4];
#pragma unroll
    for (int mf = 0; mf < 2; mf++)
#pragma unroll
        for (int nf = 0; nf < 8; nf++)
#pragma unroll
            for (int r = 0; r < 4; r++) acc[mf][nf][r] = 0.0f;

    load_stage(sm,           Ab, Bb, 0,  tid);
    load_stage(sm + STAGE_F, Ab, Bb, 32, tid);

    // fragment base offsets (in floats) for LDS.128 loads
    const int a_off0 = (wm * 32 + g) * LDA + 8 * tg;   // + mf*16*LDA + rr*8*LDA
    const int b_off0 = (wn * 64 + g) * LDA + 8 * tg;   // + nf*8*LDA

    int s = 0;
    for (int kt = 0; kt < NT; kt++) {
        if (kt < NT - 1) asm volatile("cp.async.wait_group 1;" ::: "memory");
        else             asm volatile("cp.async.wait_group 0;" ::: "memory");
        __syncthreads();

        if (kt + 2 < NT) {
            int sn = (s + 2 >= NS) ? s + 2 - NS : s + 2;
            load_stage(sm + sn * STAGE_F, Ab, Bb, (kt + 2) * 32, tid);
        }

        const uint32_t* uA = reinterpret_cast<const uint32_t*>(sm + s * STAGE_F);
        const uint32_t* uB = uA + A_FLOATS;

        // ---- load all A fragments for this 32-k tile: 8x LDS.128 ----
        uint32_t ar[2][2][8];
#pragma unroll
        for (int mf = 0; mf < 2; mf++)
#pragma unroll
            for (int rr = 0; rr < 2; rr++) {
                const uint32_t* p = uA + a_off0 + (mf * 16 + rr * 8) * LDA;
                *reinterpret_cast<uint4*>(&ar[mf][rr][0]) =
                    *reinterpret_cast<const uint4*>(p);
                *reinterpret_cast<uint4*>(&ar[mf][rr][4]) =
                    *reinterpret_cast<const uint4*>(p + 4);
            }

        // ---- per nf: 2x LDS.128 for B, then 8 MMAs ----
#pragma unroll
        for (int nf = 0; nf < 8; nf++) {
            uint32_t br[8];
            const uint32_t* p = uB + b_off0 + nf * 8 * LDA;
            *reinterpret_cast<uint4*>(&br[0]) = *reinterpret_cast<const uint4*>(p);
            *reinterpret_cast<uint4*>(&br[4]) = *reinterpret_cast<const uint4*>(p + 4);
#pragma unroll
            for (int t = 0; t < 4; t++) {
                uint32_t b2[2] = { br[2 * t], br[2 * t + 1] };
#pragma unroll
                for (int mf = 0; mf < 2; mf++) {
                    uint32_t a4[4] = { ar[mf][0][2 * t], ar[mf][1][2 * t],
                                       ar[mf][0][2 * t + 1], ar[mf][1][2 * t + 1] };
                    mma1688(acc[mf][nf], a4, b2);
                }
            }
        }
        if (++s == NS) s = 0;
    }

    // -------- epilogue --------
#pragma unroll
    for (int mf = 0; mf < 2; mf++) {
        long row0 = bm + wm * 32 + mf * 16 + g;
#pragma unroll
        for (int nf = 0; nf < 8; nf++) {
            int col = bn + wn * 64 + nf * 8 + tg * 2;
            float b0 = bias[col], b1 = bias[col + 1];
            float v0 = (acc[mf][nf][0] + b0) * scale;
            float v1 = (acc[mf][nf][1] + b1) * scale;
            float v2 = (acc[mf][nf][2] + b0) * scale;
            float v3 = (acc[mf][nf][3] + b1) * scale;
            if (do_round) { v0 = tf32r(v0); v1 = tf32r(v1); v2 = tf32r(v2); v3 = tf32r(v3); }
            *reinterpret_cast<float2*>(C + row0 * 768 + col)       = make_float2(v0, v1);
            *reinterpret_cast<float2*>(C + (row0 + 8) * 768 + col) = make_float2(v2, v3);
        }
    }
}

// ---------------------------------------------------------------------------
// tf32 pre-rounding passes
// ---------------------------------------------------------------------------
__global__ void round_x_k(const float4* __restrict__ in, float4* __restrict__ out, int n4)
{
    int i = blockIdx.x * blockDim.x + threadIdx.x;
    if (i < n4) {
        float4 v = in[i];
        v.x = tf32r(v.x); v.y = tf32r(v.y); v.z = tf32r(v.z); v.w = tf32r(v.w);
        out[i] = v;
    }
}

__global__ void round_w_k(const float4* __restrict__ w0, const float4* __restrict__ w1,
                          const float4* __restrict__ w2, const float4* __restrict__ w3,
                          float4* __restrict__ o)
{
    const float4* in = (blockIdx.y == 0) ? w0 : (blockIdx.y == 1) ? w1 :
                       (blockIdx.y == 2) ? w2 : w3;
    float4* out = o + (size_t)blockIdx.y * 147456;
    int i = blockIdx.x * blockDim.x + threadIdx.x;   // 576*256 = 147456
    float4 v = in[i];
    v.x = tf32r(v.x); v.y = tf32r(v.y); v.z = tf32r(v.z); v.w = tf32r(v.w);
    out[i] = v;
}

// ---------------------------------------------------------------------------
// Attention per (h, c) with mma.sync tf32 (unchanged from R4).
// ---------------------------------------------------------------------------
#define QK_LD  68
#define PS_LDa 132
#define VT_LD  132
#define ATTN_SMEM ((2 * 128 * QK_LD + 64 * VT_LD) * 4)   // 103424

__global__ __launch_bounds__(256, 2) void attn_mma(
    const float* __restrict__ q, const float* __restrict__ k, const float* __restrict__ v,
    const unsigned char* __restrict__ mask,
    float* __restrict__ probs, float* __restrict__ ctx, int write_probs)
{
    extern __shared__ float sm[];
    float* qs = sm;
    float* ks = sm + 128 * QK_LD;
    float* ps = sm;                      // overlays qs/ks after phase 1
    float* vt = sm + 2 * 128 * QK_LD;
    __shared__ unsigned char mask_s[128];

    const int c   = blockIdx.x;
    const int h   = blockIdx.y;
    const int tid = threadIdx.x;
    const int w    = tid >> 5;
    const int lane = tid & 31;
    const int g    = lane >> 2;
    const int tg   = lane & 3;

#pragma unroll
    for (int l = 0; l < 8; l++) {
        int idx = tid + l * 256;
        int i  = idx >> 4;
        int d4 = (idx & 15) * 4;
        size_t go = ((size_t)i * 256 + c) * 768 + h * 64 + d4;
        *reinterpret_cast<float4*>(&qs[i * QK_LD + d4]) =
            *reinterpret_cast<const float4*>(q + go);
        *reinterpret_cast<float4*>(&ks[i * QK_LD + d4]) =
            *reinterpret_cast<const float4*>(k + go);
    }
#pragma unroll
    for (int l = 0; l < 32; l++) {
        int idx = tid + l * 256;
        int d = idx & 63;
        int j = idx >> 6;
        vt[d * VT_LD + j] = v[((size_t)j * 256 + c) * 768 + h * 64 + d];
    }
    if (tid < 128) mask_s[tid] = mask[(size_t)tid * 256 + c];
    __syncthreads();

    float acc[16][4];
#pragma unroll
    for (int nf = 0; nf < 16; nf++)
#pragma unroll
        for (int r = 0; r < 4; r++) acc[nf][r] = 0.0f;

    const uint32_t* uq = reinterpret_cast<const uint32_t*>(qs);
    const uint32_t* uk = reinterpret_cast<const uint32_t*>(ks);
    const int a_base = (w * 16 + g) * QK_LD + tg;
    const int b_base = g * QK_LD + tg;

#pragma unroll
    for (int t = 0; t < 8; t++) {
        const int k0 = t * 8;
        uint32_t a[4];
        a[0] = uq[a_base + k0];
        a[1] = uq[a_base + 8 * QK_LD + k0];
        a[2] = uq[a_base + k0 + 4];
        a[3] = uq[a_base + 8 * QK_LD + k0 + 4];
#pragma unroll
        for (int nf = 0; nf < 16; nf++) {
            uint32_t b[2];
            b[0] = uk[b_base + nf * 8 * QK_LD + k0];
            b[1] = uk[b_base + nf * 8 * QK_LD + k0 + 4];
            mma1688(acc[nf], a, b);
        }
    }

#pragma unroll
    for (int nf = 0; nf < 16; nf++) {
        int j = nf * 8 + tg * 2;
        if (mask_s[j])     { acc[nf][0] = -10000.0f; acc[nf][2] = -10000.0f; }
        if (mask_s[j + 1]) { acc[nf][1] = -10000.0f; acc[nf][3] = -10000.0f; }
    }

    float m0 = -1e30f, m1 = -1e30f;
#pragma unroll
    for (int nf = 0; nf < 16; nf++) {
        m0 = fmaxf(m0, fmaxf(acc[nf][0], acc[nf][1]));
        m1 = fmaxf(m1, fmaxf(acc[nf][2], acc[nf][3]));
    }
    m0 = fmaxf(m0, __shfl_xor_sync(0xffffffffu, m0, 1));
    m0 = fmaxf(m0, __shfl_xor_sync(0xffffffffu, m0, 2));
    m1 = fmaxf(m1, __shfl_xor_sync(0xffffffffu, m1, 1));
    m1 = fmaxf(m1, __shfl_xor_sync(0xffffffffu, m1, 2));
    float s0 = 0.0f, s1 = 0.0f;
#pragma unroll
    for (int nf = 0; nf < 16; nf++) {
        acc[nf][0] = __expf(acc[nf][0] - m0);
        acc[nf][1] = __expf(acc[nf][1] - m0);
        acc[nf][2] = __expf(acc[nf][2] - m1);
        acc[nf][3] = __expf(acc[nf][3] - m1);
        s0 += acc[nf][0] + acc[nf][1];
        s1 += acc[nf][2] + acc[nf][3];
    }
    s0 += __shfl_xor_sync(0xffffffffu, s0, 1);
    s0 += __shfl_xor_sync(0xffffffffu, s0, 2);
    s1 += __shfl_xor_sync(0xffffffffu, s1, 1);
    s1 += __shfl_xor_sync(0xffffffffu, s1, 2);
    float i0 = 1.0f / s0, i1 = 1.0f / s1;
#pragma unroll
    for (int nf = 0; nf < 16; nf++) {
        acc[nf][0] *= i0; acc[nf][1] *= i0;
        acc[nf][2] *= i1; acc[nf][3] *= i1;
    }

    __syncthreads();

    const int row0 = w * 16 + g;
    if (write_probs) {
        float* pb = probs + ((size_t)h * 256 + c) * 16384;
#pragma unroll
        for (int nf = 0; nf < 16; nf++) {
            int col = nf * 8 + tg * 2;
            *reinterpret_cast<float2*>(pb + row0 * 128 + col) =
                make_float2(acc[nf][0], acc[nf][1]);
            *reinterpret_cast<float2*>(pb + (row0 + 8) * 128 + col) =
                make_float2(acc[nf][2], acc[nf][3]);
        }
    }
#pragma unroll
    for (int nf = 0; nf < 16; nf++) {
        int col = nf * 8 + tg * 2;
        *reinterpret_cast<float2*>(&ps[row0 * PS_LDa + col]) =
            make_float2(tf32r(acc[nf][0]), tf32r(acc[nf][1]));
        *reinterpret_cast<float2*>(&ps[(row0 + 8) * PS_LDa + col]) =
            make_float2(tf32r(acc[nf][2]), tf32r(acc[nf][3]));
    }
    __syncthreads();

    float acc2[8][4];
#pragma unroll
    for (int nf = 0; nf < 8; nf++)
#pragma unroll
        for (int r = 0; r < 4; r++) acc2[nf][r] = 0.0f;

    const uint32_t* up = reinterpret_cast<const uint32_t*>(ps);
    const uint32_t* uv = reinterpret_cast<const uint32_t*>(vt);
    const int a_base2 = (w * 16 + g) * PS_LDa + tg;
    const int b_base2 = g * VT_LD + tg;

#pragma unroll
    for (int t = 0; t < 16; t++) {
        const int k0 = t * 8;
        uint32_t a[4];
        a[0] = up[a_base2 + k0];
        a[1] = up[a_base2 + 8 * PS_LDa + k0];
        a[2] = up[a_base2 + k0 + 4];
        a[3] = up[a_base2 + 8 * PS_LDa + k0 + 4];
#pragma unroll
        for (int nf = 0; nf < 8; nf++) {
            uint32_t b[2];
            b[0] = uv[b_base2 + nf * 8 * VT_LD + k0];
            b[1] = uv[b_base2 + nf * 8 * VT_LD + k0 + 4];
            mma1688(acc2[nf], a, b);
        }
    }

#pragma unroll
    for (int nf = 0; nf < 8; nf++) {
        int d = nf * 8 + tg * 2;
        size_t go0 = ((size_t)row0 * 256 + c) * 768 + h * 64 + d;
        size_t go1 = ((size_t)(row0 + 8) * 256 + c) * 768 + h * 64 + d;
        *reinterpret_cast<float2*>(ctx + go0) =
            make_float2(tf32r(acc2[nf][0]), tf32r(acc2[nf][1]));
        *reinterpret_cast<float2*>(ctx + go1) =
            make_float2(tf32r(acc2[nf][2]), tf32r(acc2[nf][3]));
    }
}

// ---------------------------------------------------------------------------
extern "C" void kernel_launch(void* const* d_in, const int* in_sizes, int n_in,
                              void* d_out, int out_size)
{
    const float*         x     = (const float*)d_in[0];
    const unsigned char* pmask = (const unsigned char*)d_in[1];
    const float* bq = (const float*)d_in[3];
    const float* bk = (const float*)d_in[5];
    const float* bv = (const float*)d_in[7];
    const float* bo = (const float*)d_in[9];

    float *pq, *pk, *pv, *pctx, *pxr, *pwr;
    cudaGetSymbolAddress((void**)&pq,   g_q);
    cudaGetSymbolAddress((void**)&pk,   g_k);
    cudaGetSymbolAddress((void**)&pv,   g_v);
    cudaGetSymbolAddress((void**)&pctx, g_ctx);
    cudaGetSymbolAddress((void**)&pxr,  g_xr);
    cudaGetSymbolAddress((void**)&pwr,  g_wr);

    float* out = (float*)d_out;
    float* out_ptr   = out;
    float* probs_ptr = nullptr;
    int    do_out    = 1;
    long   os        = (long)out_size;
    if (os >= OUT_ELEMS + PROBS_ELEMS) {
        probs_ptr = out + OUT_ELEMS;
    } else if (os == PROBS_ELEMS) {
        probs_ptr = out;
        do_out = 0;
    }

    cudaFuncSetAttribute(gemm_mma, cudaFuncAttributeMaxDynamicSharedMemorySize, GEMM_SMEM);
    cudaFuncSetAttribute(attn_mma, cudaFuncAttributeMaxDynamicSharedMemorySize, ATTN_SMEM);

    // tf32 pre-rounding (rna) of GEMM inputs
    round_x_k<<<24576, 256>>>((const float4*)x, (float4*)pxr, 6291456);
    round_w_k<<<dim3(576, 4), 256>>>((const float4*)d_in[2], (const float4*)d_in[4],
                                     (const float4*)d_in[6], (const float4*)d_in[8],
                                     (float4*)pwr);

    // fused QKV projection: B = [Wq;Wk;Wv] (g_wr[0..2] contiguous), grid (18, 256)
    gemm_mma<<<dim3(18, 256), 256, GEMM_SMEM>>>(
        pxr, pwr, bq, bk, bv, pq, pk, pv, 0.125f, 1);

    attn_mma<<<dim3(256, 12), 256, ATTN_SMEM>>>(
        pq, pk, pv, pmask, probs_ptr, pctx, probs_ptr != nullptr ? 1 : 0);

    // O projection: part 0 only, grid (6, 256)
    if (do_out)
        gemm_mma<<<dim3(6, 256), 256, GEMM_SMEM>>>(
            pctx, pwr + 3 * 589824, bo, bo, bo, out_ptr, out_ptr, out_ptr, 1.0f, 0);
}

// round 6
// speedup vs baseline: 1.9604x; 1.9604x over previous
#include <cuda_runtime.h>
#include <cstdint>

#define OUT_ELEMS   25165824L   // 128*256*768
#define PROBS_ELEMS 50331648L   // 12*256*128*128

// Scratch (allocation-free rule: device globals)
__device__ float g_q[25165824];
__device__ float g_k[25165824];
__device__ float g_v[25165824];
__device__ float g_ctx[25165824];
__device__ float g_xr[25165824];
__device__ float g_wr[4][589824];   // rounded Wq,Wk,Wv,Wo; [0..2] = fused [2304,768]

// ---------------------------------------------------------------------------
// Helpers
// ---------------------------------------------------------------------------
__device__ __forceinline__ uint32_t smem_u32(const void* p) {
    uint32_t a;
    asm("{ .reg .u64 t; cvta.to.shared.u64 t, %1; cvt.u32.u64 %0, t; }" : "=r"(a) : "l"(p));
    return a;
}
__device__ __forceinline__ float tf32r(float x) {
    float y; asm("cvt.rna.tf32.f32 %0, %1;" : "=f"(y) : "f"(x)); return y;
}
__device__ __forceinline__ void cp16(uint32_t s, const void* g) {
    asm volatile("cp.async.cg.shared.global [%0], [%1], 16;"
        :: "r"(s), "l"((unsigned long long)__cvta_generic_to_global(g)) : "memory");
}
__device__ __forceinline__ void mma1688(float (&d)[4],
    uint32_t a0, uint32_t a1, uint32_t a2, uint32_t a3, uint32_t b0, uint32_t b1) {
    asm volatile(
        "mma.sync.aligned.m16n8k8.row.col.f32.tf32.tf32.f32 "
        "{%0,%1,%2,%3}, {%4,%5,%6,%7}, {%8,%9}, {%0,%1,%2,%3};"
        : "+f"(d[0]), "+f"(d[1]), "+f"(d[2]), "+f"(d[3])
        : "r"(a0), "r"(a1), "r"(a2), "r"(a3), "r"(b0), "r"(b1));
}
#define LDSM4(r0, r1, r2, r3, addr) \
    asm volatile("ldmatrix.sync.aligned.m8n8.x4.shared.b16 {%0,%1,%2,%3}, [%4];" \
        : "=r"(r0), "=r"(r1), "=r"(r2), "=r"(r3) : "r"(addr))

// ---------------------------------------------------------------------------
// tf32 mma.sync NT-GEMM, 3-stage cp.async, ldmatrix fragment loads.
// A [M,768] row-major; B fused [nparts*768, 768] row-major; N_out = 768/part.
// BM=BN=128, BK=32, 256 thr, warp 4m x 2n, warp tile 32x64.
//
// ldmatrix.x4 lane->row mapping (lq = lane/8, lr = lane%8):
//   A fragment (16m x 8k):  row = m0 + lr + 8*(lq&1),  kofs = 4*(lq>>1)
//   B fragment (16n x 8k):  row = n0 + lr + 8*(lq>>1), kofs = 4*(lq&1)
//   -> regs {a0,a1,a2,a3} match mma A slots; {b0,b1,b2,b3} = two n-tiles' {b0,b1}.
// ---------------------------------------------------------------------------
#define NS 3
#define LDA      36
#define A_FLOATS (128 * LDA)            // 4608
#define STAGE_F  (2 * A_FLOATS)         // 9216 floats (A+B)
#define GEMM_SMEM (NS * STAGE_F * 4)    // 110592 bytes
#define NT 24                           // K=768/32

__device__ __forceinline__ void load_stage(
    float* stg, const float* Ab, const float* Bb, int k0, int tid)
{
#pragma unroll
    for (int i = 0; i < 4; i++) {
        int q  = tid + i * 256;     // 0..1023
        int r  = q >> 3;            // row 0..127
        int cc = q & 7;             // 16B chunk
        cp16(smem_u32(stg + r * LDA + cc * 4),            Ab + (long)r * 768 + k0 + cc * 4);
        cp16(smem_u32(stg + A_FLOATS + r * LDA + cc * 4), Bb + (long)r * 768 + k0 + cc * 4);
    }
    asm volatile("cp.async.commit_group;" ::: "memory");
}

__global__ __launch_bounds__(256, 2) void gemm_mma(
    const float* __restrict__ A, const float* __restrict__ B,
    const float* __restrict__ bias0, const float* __restrict__ bias1,
    const float* __restrict__ bias2,
    float* __restrict__ C0, float* __restrict__ C1, float* __restrict__ C2,
    float s0, int do_round)
{
    extern __shared__ float sm[];

    const int tid  = threadIdx.x;
    const int wid  = tid >> 5;
    const int lane = tid & 31;
    const int g    = lane >> 2;
    const int tg   = lane & 3;
    const int lr   = lane & 7;
    const int lq   = lane >> 3;
    const int wm   = wid >> 1;
    const int wn   = wid & 1;
    const long bm  = (long)blockIdx.y * 128;
    const int part = blockIdx.x / 6;
    const int bn   = (blockIdx.x % 6) * 128;

    const float* bias = (part == 0) ? bias0 : (part == 1) ? bias1 : bias2;
    float* C          = (part == 0) ? C0    : (part == 1) ? C1    : C2;
    const float scale = (part == 0) ? s0 : 1.0f;

    const float* Ab = A + bm * 768;
    const float* Bb = B + (long)blockIdx.x * 128 * 768;

    float acc[2][8][4];
#pragma unroll
    for (int mf = 0; mf < 2; mf++)
#pragma unroll
        for (int nf = 0; nf < 8; nf++)
#pragma unroll
            for (int r = 0; r < 4; r++) acc[mf][nf][r] = 0.0f;

    load_stage(sm,           Ab, Bb, 0,  tid);
    load_stage(sm + STAGE_F, Ab, Bb, 32, tid);

    const uint32_t smb = smem_u32(sm);
    // per-lane ldmatrix byte offsets within a stage
    const uint32_t aoffA = ((wm * 32 + lr + 8 * (lq & 1)) * LDA + 4 * (lq >> 1)) * 4;
    const uint32_t aoffB = (uint32_t)(A_FLOATS * 4) +
                           ((wn * 64 + lr + 8 * (lq >> 1)) * LDA + 4 * (lq & 1)) * 4;

    int s = 0;
    for (int kt = 0; kt < NT; kt++) {
        if (kt < NT - 1) asm volatile("cp.async.wait_group 1;" ::: "memory");
        else             asm volatile("cp.async.wait_group 0;" ::: "memory");
        __syncthreads();

        if (kt + 2 < NT) {
            int sn = (s + 2 >= NS) ? s + 2 - NS : s + 2;
            load_stage(sm + sn * STAGE_F, Ab, Bb, (kt + 2) * 32, tid);
        }

        const uint32_t sb  = smb + (uint32_t)(s * STAGE_F * 4);
        const uint32_t aA0 = sb + aoffA;                 // mf=0
        const uint32_t aA1 = aA0 + 16 * LDA * 4;         // mf=1
        const uint32_t aB  = sb + aoffB;                 // pair stride 16*LDA*4

#pragma unroll
        for (int t = 0; t < 4; t++) {
            const uint32_t ko = t * 32;                  // 8 floats per t
            uint32_t a0[4], a1[4];
            LDSM4(a0[0], a0[1], a0[2], a0[3], aA0 + ko);
            LDSM4(a1[0], a1[1], a1[2], a1[3], aA1 + ko);
#pragma unroll
            for (int pr = 0; pr < 4; pr++) {
                uint32_t b0, b1, b2, b3;
                LDSM4(b0, b1, b2, b3, aB + pr * (16 * LDA * 4) + ko);
                mma1688(acc[0][2 * pr],     a0[0], a0[1], a0[2], a0[3], b0, b1);
                mma1688(acc[1][2 * pr],     a1[0], a1[1], a1[2], a1[3], b0, b1);
                mma1688(acc[0][2 * pr + 1], a0[0], a0[1], a0[2], a0[3], b2, b3);
                mma1688(acc[1][2 * pr + 1], a1[0], a1[1], a1[2], a1[3], b2, b3);
            }
        }
        if (++s == NS) s = 0;
    }

    // -------- epilogue --------
#pragma unroll
    for (int mf = 0; mf < 2; mf++) {
        long row0 = bm + wm * 32 + mf * 16 + g;
#pragma unroll
        for (int nf = 0; nf < 8; nf++) {
            int col = bn + wn * 64 + nf * 8 + tg * 2;
            float b0 = bias[col], b1 = bias[col + 1];
            float v0 = (acc[mf][nf][0] + b0) * scale;
            float v1 = (acc[mf][nf][1] + b1) * scale;
            float v2 = (acc[mf][nf][2] + b0) * scale;
            float v3 = (acc[mf][nf][3] + b1) * scale;
            if (do_round) { v0 = tf32r(v0); v1 = tf32r(v1); v2 = tf32r(v2); v3 = tf32r(v3); }
            *reinterpret_cast<float2*>(C + row0 * 768 + col)       = make_float2(v0, v1);
            *reinterpret_cast<float2*>(C + (row0 + 8) * 768 + col) = make_float2(v2, v3);
        }
    }
}

// ---------------------------------------------------------------------------
// tf32 pre-rounding passes
// ---------------------------------------------------------------------------
__global__ void round_x_k(const float4* __restrict__ in, float4* __restrict__ out, int n4)
{
    int i = blockIdx.x * blockDim.x + threadIdx.x;
    if (i < n4) {
        float4 v = in[i];
        v.x = tf32r(v.x); v.y = tf32r(v.y); v.z = tf32r(v.z); v.w = tf32r(v.w);
        out[i] = v;
    }
}

__global__ void round_w_k(const float4* __restrict__ w0, const float4* __restrict__ w1,
                          const float4* __restrict__ w2, const float4* __restrict__ w3,
                          float4* __restrict__ o)
{
    const float4* in = (blockIdx.y == 0) ? w0 : (blockIdx.y == 1) ? w1 :
                       (blockIdx.y == 2) ? w2 : w3;
    float4* out = o + (size_t)blockIdx.y * 147456;
    int i = blockIdx.x * blockDim.x + threadIdx.x;   // 576*256 = 147456
    float4 v = in[i];
    v.x = tf32r(v.x); v.y = tf32r(v.y); v.z = tf32r(v.z); v.w = tf32r(v.w);
    out[i] = v;
}

// ---------------------------------------------------------------------------
// Attention per (h, c), mma.sync tf32 with ldmatrix fragment loads.
// ---------------------------------------------------------------------------
#define QK_LD  68
#define PS_LDa 132
#define VT_LD  132
#define ATTN_SMEM ((2 * 128 * QK_LD + 64 * VT_LD) * 4)   // 103424

__global__ __launch_bounds__(256, 2) void attn_mma(
    const float* __restrict__ q, const float* __restrict__ k, const float* __restrict__ v,
    const unsigned char* __restrict__ mask,
    float* __restrict__ probs, float* __restrict__ ctx, int write_probs)
{
    extern __shared__ float sm[];
    float* qs = sm;
    float* ks = sm + 128 * QK_LD;
    float* ps = sm;                      // overlays qs/ks after phase 1
    float* vt = sm + 2 * 128 * QK_LD;
    __shared__ unsigned char mask_s[128];

    const int c   = blockIdx.x;
    const int h   = blockIdx.y;
    const int tid = threadIdx.x;
    const int w    = tid >> 5;
    const int lane = tid & 31;
    const int g    = lane >> 2;
    const int tg   = lane & 3;
    const int lr   = lane & 7;
    const int lq   = lane >> 3;

#pragma unroll
    for (int l = 0; l < 8; l++) {
        int idx = tid + l * 256;
        int i  = idx >> 4;
        int d4 = (idx & 15) * 4;
        size_t go = ((size_t)i * 256 + c) * 768 + h * 64 + d4;
        *reinterpret_cast<float4*>(&qs[i * QK_LD + d4]) =
            *reinterpret_cast<const float4*>(q + go);
        *reinterpret_cast<float4*>(&ks[i * QK_LD + d4]) =
            *reinterpret_cast<const float4*>(k + go);
    }
#pragma unroll
    for (int l = 0; l < 32; l++) {
        int idx = tid + l * 256;
        int d = idx & 63;
        int j = idx >> 6;
        vt[d * VT_LD + j] = v[((size_t)j * 256 + c) * 768 + h * 64 + d];
    }
    if (tid < 128) mask_s[tid] = mask[(size_t)tid * 256 + c];
    __syncthreads();

    // ---- phase 1: S = Q K^T, warp tile 16x128 ----
    float acc[16][4];
#pragma unroll
    for (int nf = 0; nf < 16; nf++)
#pragma unroll
        for (int r = 0; r < 4; r++) acc[nf][r] = 0.0f;

    const uint32_t qsb = smem_u32(qs);
    const uint32_t ksb = smem_u32(ks);
    const uint32_t aQ = qsb + ((w * 16 + lr + 8 * (lq & 1)) * QK_LD + 4 * (lq >> 1)) * 4;
    const uint32_t aK = ksb + ((lr + 8 * (lq >> 1)) * QK_LD + 4 * (lq & 1)) * 4;

#pragma unroll
    for (int t = 0; t < 8; t++) {
        const uint32_t ko = t * 32;
        uint32_t a0[4];
        LDSM4(a0[0], a0[1], a0[2], a0[3], aQ + ko);
#pragma unroll
        for (int pr = 0; pr < 8; pr++) {
            uint32_t b0, b1, b2, b3;
            LDSM4(b0, b1, b2, b3, aK + pr * (16 * QK_LD * 4) + ko);
            mma1688(acc[2 * pr],     a0[0], a0[1], a0[2], a0[3], b0, b1);
            mma1688(acc[2 * pr + 1], a0[0], a0[1], a0[2], a0[3], b2, b3);
        }
    }

    // ---- mask ----
#pragma unroll
    for (int nf = 0; nf < 16; nf++) {
        int j = nf * 8 + tg * 2;
        if (mask_s[j])     { acc[nf][0] = -10000.0f; acc[nf][2] = -10000.0f; }
        if (mask_s[j + 1]) { acc[nf][1] = -10000.0f; acc[nf][3] = -10000.0f; }
    }

    // ---- softmax ----
    float m0 = -1e30f, m1 = -1e30f;
#pragma unroll
    for (int nf = 0; nf < 16; nf++) {
        m0 = fmaxf(m0, fmaxf(acc[nf][0], acc[nf][1]));
        m1 = fmaxf(m1, fmaxf(acc[nf][2], acc[nf][3]));
    }
    m0 = fmaxf(m0, __shfl_xor_sync(0xffffffffu, m0, 1));
    m0 = fmaxf(m0, __shfl_xor_sync(0xffffffffu, m0, 2));
    m1 = fmaxf(m1, __shfl_xor_sync(0xffffffffu, m1, 1));
    m1 = fmaxf(m1, __shfl_xor_sync(0xffffffffu, m1, 2));
    float s0 = 0.0f, s1 = 0.0f;
#pragma unroll
    for (int nf = 0; nf < 16; nf++) {
        acc[nf][0] = __expf(acc[nf][0] - m0);
        acc[nf][1] = __expf(acc[nf][1] - m0);
        acc[nf][2] = __expf(acc[nf][2] - m1);
        acc[nf][3] = __expf(acc[nf][3] - m1);
        s0 += acc[nf][0] + acc[nf][1];
        s1 += acc[nf][2] + acc[nf][3];
    }
    s0 += __shfl_xor_sync(0xffffffffu, s0, 1);
    s0 += __shfl_xor_sync(0xffffffffu, s0, 2);
    s1 += __shfl_xor_sync(0xffffffffu, s1, 1);
    s1 += __shfl_xor_sync(0xffffffffu, s1, 2);
    float i0 = 1.0f / s0, i1 = 1.0f / s1;
#pragma unroll
    for (int nf = 0; nf < 16; nf++) {
        acc[nf][0] *= i0; acc[nf][1] *= i0;
        acc[nf][2] *= i1; acc[nf][3] *= i1;
    }

    __syncthreads();   // all warps done reading qs/ks

    // ---- P -> smem (rounded); probs -> gmem (unrounded) ----
    const int row0 = w * 16 + g;
    if (write_probs) {
        float* pb = probs + ((size_t)h * 256 + c) * 16384;
#pragma unroll
        for (int nf = 0; nf < 16; nf++) {
            int col = nf * 8 + tg * 2;
            *reinterpret_cast<float2*>(pb + row0 * 128 + col) =
                make_float2(acc[nf][0], acc[nf][1]);
            *reinterpret_cast<float2*>(pb + (row0 + 8) * 128 + col) =
                make_float2(acc[nf][2], acc[nf][3]);
        }
    }
#pragma unroll
    for (int nf = 0; nf < 16; nf++) {
        int col = nf * 8 + tg * 2;
        *reinterpret_cast<float2*>(&ps[row0 * PS_LDa + col]) =
            make_float2(tf32r(acc[nf][0]), tf32r(acc[nf][1]));
        *reinterpret_cast<float2*>(&ps[(row0 + 8) * PS_LDa + col]) =
            make_float2(tf32r(acc[nf][2]), tf32r(acc[nf][3]));
    }
    __syncthreads();

    // ---- phase 2: ctx = P V, warp tile 16x64 ----
    float acc2[8][4];
#pragma unroll
    for (int nf = 0; nf < 8; nf++)
#pragma unroll
        for (int r = 0; r < 4; r++) acc2[nf][r] = 0.0f;

    const uint32_t psb = smem_u32(ps);
    const uint32_t vtb = smem_u32(vt);
    const uint32_t aP = psb + ((w * 16 + lr + 8 * (lq & 1)) * PS_LDa + 4 * (lq >> 1)) * 4;
    const uint32_t aV = vtb + ((lr + 8 * (lq >> 1)) * VT_LD + 4 * (lq & 1)) * 4;

#pragma unroll
    for (int t = 0; t < 16; t++) {
        const uint32_t ko = t * 32;
        uint32_t a0[4];
        LDSM4(a0[0], a0[1], a0[2], a0[3], aP + ko);
#pragma unroll
        for (int pr = 0; pr < 4; pr++) {
            uint32_t b0, b1, b2, b3;
            LDSM4(b0, b1, b2, b3, aV + pr * (16 * VT_LD * 4) + ko);
            mma1688(acc2[2 * pr],     a0[0], a0[1], a0[2], a0[3], b0, b1);
            mma1688(acc2[2 * pr + 1], a0[0], a0[1], a0[2], a0[3], b2, b3);
        }
    }

    // ---- ctx epilogue (tf32-rounded: feeds O projection) ----
#pragma unroll
    for (int nf = 0; nf < 8; nf++) {
        int d = nf * 8 + tg * 2;
        size_t go0 = ((size_t)row0 * 256 + c) * 768 + h * 64 + d;
        size_t go1 = ((size_t)(row0 + 8) * 256 + c) * 768 + h * 64 + d;
        *reinterpret_cast<float2*>(ctx + go0) =
            make_float2(tf32r(acc2[nf][0]), tf32r(acc2[nf][1]));
        *reinterpret_cast<float2*>(ctx + go1) =
            make_float2(tf32r(acc2[nf][2]), tf32r(acc2[nf][3]));
    }
}

// ---------------------------------------------------------------------------
extern "C" void kernel_launch(void* const* d_in, const int* in_sizes, int n_in,
                              void* d_out, int out_size)
{
    const float*         x     = (const float*)d_in[0];
    const unsigned char* pmask = (const unsigned char*)d_in[1];
    const float* bq = (const float*)d_in[3];
    const float* bk = (const float*)d_in[5];
    const float* bv = (const float*)d_in[7];
    const float* bo = (const float*)d_in[9];

    float *pq, *pk, *pv, *pctx, *pxr, *pwr;
    cudaGetSymbolAddress((void**)&pq,   g_q);
    cudaGetSymbolAddress((void**)&pk,   g_k);
    cudaGetSymbolAddress((void**)&pv,   g_v);
    cudaGetSymbolAddress((void**)&pctx, g_ctx);
    cudaGetSymbolAddress((void**)&pxr,  g_xr);
    cudaGetSymbolAddress((void**)&pwr,  g_wr);

    float* out = (float*)d_out;
    float* out_ptr   = out;
    float* probs_ptr = nullptr;
    int    do_out    = 1;
    long   os        = (long)out_size;
    if (os >= OUT_ELEMS + PROBS_ELEMS) {
        probs_ptr = out + OUT_ELEMS;
    } else if (os == PROBS_ELEMS) {
        probs_ptr = out;
        do_out = 0;
    }

    cudaFuncSetAttribute(gemm_mma, cudaFuncAttributeMaxDynamicSharedMemorySize, GEMM_SMEM);
    cudaFuncSetAttribute(attn_mma, cudaFuncAttributeMaxDynamicSharedMemorySize, ATTN_SMEM);

    // tf32 pre-rounding (rna) of GEMM inputs
    round_x_k<<<24576, 256>>>((const float4*)x, (float4*)pxr, 6291456);
    round_w_k<<<dim3(576, 4), 256>>>((const float4*)d_in[2], (const float4*)d_in[4],
                                     (const float4*)d_in[6], (const float4*)d_in[8],
                                     (float4*)pwr);

    // fused QKV projection: B = [Wq;Wk;Wv] (g_wr[0..2] contiguous), grid (18, 256)
    gemm_mma<<<dim3(18, 256), 256, GEMM_SMEM>>>(
        pxr, pwr, bq, bk, bv, pq, pk, pv, 0.125f, 1);

    attn_mma<<<dim3(256, 12), 256, ATTN_SMEM>>>(
        pq, pk, pv, pmask, probs_ptr, pctx, probs_ptr != nullptr ? 1 : 0);

    // O projection: part 0 only, grid (6, 256)
    if (do_out)
        gemm_mma<<<dim3(6, 256), 256, GEMM_SMEM>>>(
            pctx, pwr + 3 * 589824, bo, bo, bo, out_ptr, out_ptr, out_ptr, 1.0f, 0);
}

// round 7
// speedup vs baseline: 1.9684x; 1.0041x over previous
#include <cuda_runtime.h>
#include <cuda_fp16.h>
#include <cstdint>

#define OUT_ELEMS   25165824L   // 128*256*768
#define PROBS_ELEMS 50331648L   // 12*256*128*128

// Scratch (allocation-free rule: device globals)
__device__ float g_q[25165824];
__device__ float g_k[25165824];
__device__ float g_v[25165824];
__device__ float g_ctx[25165824];
__device__ float g_xr[25165824];
__device__ float g_wr[4][589824];   // rounded Wq,Wk,Wv,Wo; [0..2] = fused [2304,768]

// ---------------------------------------------------------------------------
// Helpers
// ---------------------------------------------------------------------------
__device__ __forceinline__ uint32_t smem_u32(const void* p) {
    uint32_t a;
    asm("{ .reg .u64 t; cvta.to.shared.u64 t, %1; cvt.u32.u64 %0, t; }" : "=r"(a) : "l"(p));
    return a;
}
__device__ __forceinline__ float tf32r(float x) {
    float y; asm("cvt.rna.tf32.f32 %0, %1;" : "=f"(y) : "f"(x)); return y;
}
__device__ __forceinline__ void cp16(uint32_t s, const void* g) {
    asm volatile("cp.async.cg.shared.global [%0], [%1], 16;"
        :: "r"(s), "l"((unsigned long long)__cvta_generic_to_global(g)) : "memory");
}
__device__ __forceinline__ void mma1688(float (&d)[4],
    uint32_t a0, uint32_t a1, uint32_t a2, uint32_t a3, uint32_t b0, uint32_t b1) {
    asm volatile(
        "mma.sync.aligned.m16n8k8.row.col.f32.tf32.tf32.f32 "
        "{%0,%1,%2,%3}, {%4,%5,%6,%7}, {%8,%9}, {%0,%1,%2,%3};"
        : "+f"(d[0]), "+f"(d[1]), "+f"(d[2]), "+f"(d[3])
        : "r"(a0), "r"(a1), "r"(a2), "r"(a3), "r"(b0), "r"(b1));
}
#define LDSM4(r0, r1, r2, r3, addr) \
    asm volatile("ldmatrix.sync.aligned.m8n8.x4.shared.b16 {%0,%1,%2,%3}, [%4];" \
        : "=r"(r0), "=r"(r1), "=r"(r2), "=r"(r3) : "r"(addr))

// ---------------------------------------------------------------------------
// tf32 mma.sync NT-GEMM, 3-stage cp.async, ldmatrix fragment loads.
// A [M,768] row-major; B fused [nparts*768, 768] row-major; N_out = 768/part.
// BM=BN=128, BK=32, 256 thr, warp 4m x 2n, warp tile 32x64.
// ---------------------------------------------------------------------------
#define NS 3
#define LDA      36
#define A_FLOATS (128 * LDA)            // 4608
#define STAGE_F  (2 * A_FLOATS)         // 9216 floats (A+B)
#define GEMM_SMEM (NS * STAGE_F * 4)    // 110592 bytes
#define NT 24                           // K=768/32

__device__ __forceinline__ void load_stage(
    float* stg, const float* Ab, const float* Bb, int k0, int tid)
{
#pragma unroll
    for (int i = 0; i < 4; i++) {
        int q  = tid + i * 256;     // 0..1023
        int r  = q >> 3;            // row 0..127
        int cc = q & 7;             // 16B chunk
        cp16(smem_u32(stg + r * LDA + cc * 4),            Ab + (long)r * 768 + k0 + cc * 4);
        cp16(smem_u32(stg + A_FLOATS + r * LDA + cc * 4), Bb + (long)r * 768 + k0 + cc * 4);
    }
    asm volatile("cp.async.commit_group;" ::: "memory");
}

__global__ __launch_bounds__(256, 2) void gemm_mma(
    const float* __restrict__ A, const float* __restrict__ B,
    const float* __restrict__ bias0, const float* __restrict__ bias1,
    const float* __restrict__ bias2,
    float* __restrict__ C0, float* __restrict__ C1, float* __restrict__ C2,
    float s0, int do_round)
{
    extern __shared__ float sm[];

    const int tid  = threadIdx.x;
    const int wid  = tid >> 5;
    const int lane = tid & 31;
    const int g    = lane >> 2;
    const int tg   = lane & 3;
    const int lr   = lane & 7;
    const int lq   = lane >> 3;
    const int wm   = wid >> 1;
    const int wn   = wid & 1;
    const long bm  = (long)blockIdx.y * 128;
    const int part = blockIdx.x / 6;
    const int bn   = (blockIdx.x % 6) * 128;

    const float* bias = (part == 0) ? bias0 : (part == 1) ? bias1 : bias2;
    float* C          = (part == 0) ? C0    : (part == 1) ? C1    : C2;
    const float scale = (part == 0) ? s0 : 1.0f;

    const float* Ab = A + bm * 768;
    const float* Bb = B + (long)blockIdx.x * 128 * 768;

    float acc[2][8][4];
#pragma unroll
    for (int mf = 0; mf < 2; mf++)
#pragma unroll
        for (int nf = 0; nf < 8; nf++)
#pragma unroll
            for (int r = 0; r < 4; r++) acc[mf][nf][r] = 0.0f;

    load_stage(sm,           Ab, Bb, 0,  tid);
    load_stage(sm + STAGE_F, Ab, Bb, 32, tid);

    const uint32_t smb = smem_u32(sm);
    const uint32_t aoffA = ((wm * 32 + lr + 8 * (lq & 1)) * LDA + 4 * (lq >> 1)) * 4;
    const uint32_t aoffB = (uint32_t)(A_FLOATS * 4) +
                           ((wn * 64 + lr + 8 * (lq >> 1)) * LDA + 4 * (lq & 1)) * 4;

    int s = 0;
    for (int kt = 0; kt < NT; kt++) {
        if (kt < NT - 1) asm volatile("cp.async.wait_group 1;" ::: "memory");
        else             asm volatile("cp.async.wait_group 0;" ::: "memory");
        __syncthreads();

        if (kt + 2 < NT) {
            int sn = (s + 2 >= NS) ? s + 2 - NS : s + 2;
            load_stage(sm + sn * STAGE_F, Ab, Bb, (kt + 2) * 32, tid);
        }

        const uint32_t sb  = smb + (uint32_t)(s * STAGE_F * 4);
        const uint32_t aA0 = sb + aoffA;
        const uint32_t aA1 = aA0 + 16 * LDA * 4;
        const uint32_t aB  = sb + aoffB;

#pragma unroll
        for (int t = 0; t < 4; t++) {
            const uint32_t ko = t * 32;
            // hoist ALL fragment loads for this t before any mma
            uint32_t a0[4], a1[4], b[4][4];
            LDSM4(a0[0], a0[1], a0[2], a0[3], aA0 + ko);
            LDSM4(a1[0], a1[1], a1[2], a1[3], aA1 + ko);
            LDSM4(b[0][0], b[0][1], b[0][2], b[0][3], aB + 0 * (16 * LDA * 4) + ko);
            LDSM4(b[1][0], b[1][1], b[1][2], b[1][3], aB + 1 * (16 * LDA * 4) + ko);
            LDSM4(b[2][0], b[2][1], b[2][2], b[2][3], aB + 2 * (16 * LDA * 4) + ko);
            LDSM4(b[3][0], b[3][1], b[3][2], b[3][3], aB + 3 * (16 * LDA * 4) + ko);
#pragma unroll
            for (int pr = 0; pr < 4; pr++) {
                mma1688(acc[0][2 * pr],     a0[0], a0[1], a0[2], a0[3], b[pr][0], b[pr][1]);
                mma1688(acc[1][2 * pr],     a1[0], a1[1], a1[2], a1[3], b[pr][0], b[pr][1]);
                mma1688(acc[0][2 * pr + 1], a0[0], a0[1], a0[2], a0[3], b[pr][2], b[pr][3]);
                mma1688(acc[1][2 * pr + 1], a1[0], a1[1], a1[2], a1[3], b[pr][2], b[pr][3]);
            }
        }
        if (++s == NS) s = 0;
    }

    // -------- epilogue --------
#pragma unroll
    for (int mf = 0; mf < 2; mf++) {
        long row0 = bm + wm * 32 + mf * 16 + g;
#pragma unroll
        for (int nf = 0; nf < 8; nf++) {
            int col = bn + wn * 64 + nf * 8 + tg * 2;
            float b0 = bias[col], b1 = bias[col + 1];
            float v0 = (acc[mf][nf][0] + b0) * scale;
            float v1 = (acc[mf][nf][1] + b1) * scale;
            float v2 = (acc[mf][nf][2] + b0) * scale;
            float v3 = (acc[mf][nf][3] + b1) * scale;
            if (do_round) { v0 = tf32r(v0); v1 = tf32r(v1); v2 = tf32r(v2); v3 = tf32r(v3); }
            *reinterpret_cast<float2*>(C + row0 * 768 + col)       = make_float2(v0, v1);
            *reinterpret_cast<float2*>(C + (row0 + 8) * 768 + col) = make_float2(v2, v3);
        }
    }
}

// ---------------------------------------------------------------------------
// tf32 pre-rounding passes
// ---------------------------------------------------------------------------
__global__ void round_x_k(const float4* __restrict__ in, float4* __restrict__ out, int n4)
{
    int i = blockIdx.x * blockDim.x + threadIdx.x;
    if (i < n4) {
        float4 v = in[i];
        v.x = tf32r(v.x); v.y = tf32r(v.y); v.z = tf32r(v.z); v.w = tf32r(v.w);
        out[i] = v;
    }
}

__global__ void round_w_k(const float4* __restrict__ w0, const float4* __restrict__ w1,
                          const float4* __restrict__ w2, const float4* __restrict__ w3,
                          float4* __restrict__ o)
{
    const float4* in = (blockIdx.y == 0) ? w0 : (blockIdx.y == 1) ? w1 :
                       (blockIdx.y == 2) ? w2 : w3;
    float4* out = o + (size_t)blockIdx.y * 147456;
    int i = blockIdx.x * blockDim.x + threadIdx.x;   // 576*256 = 147456
    float4 v = in[i];
    v.x = tf32r(v.x); v.y = tf32r(v.y); v.z = tf32r(v.z); v.w = tf32r(v.w);
    out[i] = v;
}

// ---------------------------------------------------------------------------
// Attention per (h, c), mma.sync tf32 + ldmatrix; softmax via ex2.approx.f16x2.
// q arrives pre-scaled by 0.125*log2(e): scores are in log2 domain, so
// probs = exp2(S' - m') / sum  == softmax(S)  (temperature reparametrization).
// ---------------------------------------------------------------------------
#define QK_LD  68
#define PS_LDa 132
#define VT_LD  132
#define ATTN_SMEM ((2 * 128 * QK_LD + 64 * VT_LD) * 4)   // 103424

__global__ __launch_bounds__(256, 2) void attn_mma(
    const float* __restrict__ q, const float* __restrict__ k, const float* __restrict__ v,
    const unsigned char* __restrict__ mask,
    float* __restrict__ probs, float* __restrict__ ctx, int write_probs)
{
    extern __shared__ float sm[];
    float* qs = sm;
    float* ks = sm + 128 * QK_LD;
    float* ps = sm;                      // overlays qs/ks after phase 1
    float* vt = sm + 2 * 128 * QK_LD;
    __shared__ unsigned char mask_s[128];

    const int c   = blockIdx.x;
    const int h   = blockIdx.y;
    const int tid = threadIdx.x;
    const int w    = tid >> 5;
    const int lane = tid & 31;
    const int g    = lane >> 2;
    const int tg   = lane & 3;
    const int lr   = lane & 7;
    const int lq   = lane >> 3;

#pragma unroll
    for (int l = 0; l < 8; l++) {
        int idx = tid + l * 256;
        int i  = idx >> 4;
        int d4 = (idx & 15) * 4;
        size_t go = ((size_t)i * 256 + c) * 768 + h * 64 + d4;
        *reinterpret_cast<float4*>(&qs[i * QK_LD + d4]) =
            *reinterpret_cast<const float4*>(q + go);
        *reinterpret_cast<float4*>(&ks[i * QK_LD + d4]) =
            *reinterpret_cast<const float4*>(k + go);
    }
#pragma unroll
    for (int l = 0; l < 32; l++) {
        int idx = tid + l * 256;
        int d = idx & 63;
        int j = idx >> 6;
        vt[d * VT_LD + j] = v[((size_t)j * 256 + c) * 768 + h * 64 + d];
    }
    if (tid < 128) mask_s[tid] = mask[(size_t)tid * 256 + c];
    __syncthreads();

    // ---- phase 1: S' = Q' K^T (log2 domain), warp tile 16x128 ----
    float acc[16][4];
#pragma unroll
    for (int nf = 0; nf < 16; nf++)
#pragma unroll
        for (int r = 0; r < 4; r++) acc[nf][r] = 0.0f;

    const uint32_t qsb = smem_u32(qs);
    const uint32_t ksb = smem_u32(ks);
    const uint32_t aQ = qsb + ((w * 16 + lr + 8 * (lq & 1)) * QK_LD + 4 * (lq >> 1)) * 4;
    const uint32_t aK = ksb + ((lr + 8 * (lq >> 1)) * QK_LD + 4 * (lq & 1)) * 4;

#pragma unroll
    for (int t = 0; t < 8; t++) {
        const uint32_t ko = t * 32;
        uint32_t a0[4];
        LDSM4(a0[0], a0[1], a0[2], a0[3], aQ + ko);
#pragma unroll
        for (int pr = 0; pr < 8; pr++) {
            uint32_t b0, b1, b2, b3;
            LDSM4(b0, b1, b2, b3, aK + pr * (16 * QK_LD * 4) + ko);
            mma1688(acc[2 * pr],     a0[0], a0[1], a0[2], a0[3], b0, b1);
            mma1688(acc[2 * pr + 1], a0[0], a0[1], a0[2], a0[3], b2, b3);
        }
    }

    // ---- mask (any very-negative value; exp2 underflows to 0) ----
#pragma unroll
    for (int nf = 0; nf < 16; nf++) {
        int j = nf * 8 + tg * 2;
        if (mask_s[j])     { acc[nf][0] = -14000.0f; acc[nf][2] = -14000.0f; }
        if (mask_s[j + 1]) { acc[nf][1] = -14000.0f; acc[nf][3] = -14000.0f; }
    }

    // ---- softmax in log2 domain, exp2 two-at-a-time in fp16 ----
    float m0 = -1e30f, m1 = -1e30f;
#pragma unroll
    for (int nf = 0; nf < 16; nf++) {
        m0 = fmaxf(m0, fmaxf(acc[nf][0], acc[nf][1]));
        m1 = fmaxf(m1, fmaxf(acc[nf][2], acc[nf][3]));
    }
    m0 = fmaxf(m0, __shfl_xor_sync(0xffffffffu, m0, 1));
    m0 = fmaxf(m0, __shfl_xor_sync(0xffffffffu, m0, 2));
    m1 = fmaxf(m1, __shfl_xor_sync(0xffffffffu, m1, 1));
    m1 = fmaxf(m1, __shfl_xor_sync(0xffffffffu, m1, 2));
    float s0 = 0.0f, s1 = 0.0f;
#pragma unroll
    for (int nf = 0; nf < 16; nf++) {
        half2 h01 = __floats2half2_rn(acc[nf][0] - m0, acc[nf][1] - m0);
        half2 h23 = __floats2half2_rn(acc[nf][2] - m1, acc[nf][3] - m1);
        h01 = h2exp2(h01);
        h23 = h2exp2(h23);
        float2 e01 = __half22float2(h01);
        float2 e23 = __half22float2(h23);
        acc[nf][0] = e01.x; acc[nf][1] = e01.y;
        acc[nf][2] = e23.x; acc[nf][3] = e23.y;
        s0 += e01.x + e01.y;
        s1 += e23.x + e23.y;
    }
    s0 += __shfl_xor_sync(0xffffffffu, s0, 1);
    s0 += __shfl_xor_sync(0xffffffffu, s0, 2);
    s1 += __shfl_xor_sync(0xffffffffu, s1, 1);
    s1 += __shfl_xor_sync(0xffffffffu, s1, 2);
    float i0 = 1.0f / s0, i1 = 1.0f / s1;
#pragma unroll
    for (int nf = 0; nf < 16; nf++) {
        acc[nf][0] *= i0; acc[nf][1] *= i0;
        acc[nf][2] *= i1; acc[nf][3] *= i1;
    }

    __syncthreads();   // all warps done reading qs/ks

    // ---- P -> smem (rounded); probs -> gmem ----
    const int row0 = w * 16 + g;
    if (write_probs) {
        float* pb = probs + ((size_t)h * 256 + c) * 16384;
#pragma unroll
        for (int nf = 0; nf < 16; nf++) {
            int col = nf * 8 + tg * 2;
            *reinterpret_cast<float2*>(pb + row0 * 128 + col) =
                make_float2(acc[nf][0], acc[nf][1]);
            *reinterpret_cast<float2*>(pb + (row0 + 8) * 128 + col) =
                make_float2(acc[nf][2], acc[nf][3]);
        }
    }
#pragma unroll
    for (int nf = 0; nf < 16; nf++) {
        int col = nf * 8 + tg * 2;
        *reinterpret_cast<float2*>(&ps[row0 * PS_LDa + col]) =
            make_float2(tf32r(acc[nf][0]), tf32r(acc[nf][1]));
        *reinterpret_cast<float2*>(&ps[(row0 + 8) * PS_LDa + col]) =
            make_float2(tf32r(acc[nf][2]), tf32r(acc[nf][3]));
    }
    __syncthreads();

    // ---- phase 2: ctx = P V, warp tile 16x64 ----
    float acc2[8][4];
#pragma unroll
    for (int nf = 0; nf < 8; nf++)
#pragma unroll
        for (int r = 0; r < 4; r++) acc2[nf][r] = 0.0f;

    const uint32_t psb = smem_u32(ps);
    const uint32_t vtb = smem_u32(vt);
    const uint32_t aP = psb + ((w * 16 + lr + 8 * (lq & 1)) * PS_LDa + 4 * (lq >> 1)) * 4;
    const uint32_t aV = vtb + ((lr + 8 * (lq >> 1)) * VT_LD + 4 * (lq & 1)) * 4;

#pragma unroll
    for (int t = 0; t < 16; t++) {
        const uint32_t ko = t * 32;
        uint32_t a0[4];
        LDSM4(a0[0], a0[1], a0[2], a0[3], aP + ko);
#pragma unroll
        for (int pr = 0; pr < 4; pr++) {
            uint32_t b0, b1, b2, b3;
            LDSM4(b0, b1, b2, b3, aV + pr * (16 * VT_LD * 4) + ko);
            mma1688(acc2[2 * pr],     a0[0], a0[1], a0[2], a0[3], b0, b1);
            mma1688(acc2[2 * pr + 1], a0[0], a0[1], a0[2], a0[3], b2, b3);
        }
    }

    // ---- ctx epilogue (tf32-rounded: feeds O projection) ----
#pragma unroll
    for (int nf = 0; nf < 8; nf++) {
        int d = nf * 8 + tg * 2;
        size_t go0 = ((size_t)row0 * 256 + c) * 768 + h * 64 + d;
        size_t go1 = ((size_t)(row0 + 8) * 256 + c) * 768 + h * 64 + d;
        *reinterpret_cast<float2*>(ctx + go0) =
            make_float2(tf32r(acc2[nf][0]), tf32r(acc2[nf][1]));
        *reinterpret_cast<float2*>(ctx + go1) =
            make_float2(tf32r(acc2[nf][2]), tf32r(acc2[nf][3]));
    }
}

// ---------------------------------------------------------------------------
extern "C" void kernel_launch(void* const* d_in, const int* in_sizes, int n_in,
                              void* d_out, int out_size)
{
    const float*         x     = (const float*)d_in[0];
    const unsigned char* pmask = (const unsigned char*)d_in[1];
    const float* bq = (const float*)d_in[3];
    const float* bk = (const float*)d_in[5];
    const float* bv = (const float*)d_in[7];
    const float* bo = (const float*)d_in[9];

    float *pq, *pk, *pv, *pctx, *pxr, *pwr;
    cudaGetSymbolAddress((void**)&pq,   g_q);
    cudaGetSymbolAddress((void**)&pk,   g_k);
    cudaGetSymbolAddress((void**)&pv,   g_v);
    cudaGetSymbolAddress((void**)&pctx, g_ctx);
    cudaGetSymbolAddress((void**)&pxr,  g_xr);
    cudaGetSymbolAddress((void**)&pwr,  g_wr);

    float* out = (float*)d_out;
    float* out_ptr   = out;
    float* probs_ptr = nullptr;
    int    do_out    = 1;
    long   os        = (long)out_size;
    if (os >= OUT_ELEMS + PROBS_ELEMS) {
        probs_ptr = out + OUT_ELEMS;
    } else if (os == PROBS_ELEMS) {
        probs_ptr = out;
        do_out = 0;
    }

    cudaFuncSetAttribute(gemm_mma, cudaFuncAttributeMaxDynamicSharedMemorySize, GEMM_SMEM);
    cudaFuncSetAttribute(attn_mma, cudaFuncAttributeMaxDynamicSharedMemorySize, ATTN_SMEM);

    // tf32 pre-rounding (rna) of GEMM inputs
    round_x_k<<<24576, 256>>>((const float4*)x, (float4*)pxr, 6291456);
    round_w_k<<<dim3(576, 4), 256>>>((const float4*)d_in[2], (const float4*)d_in[4],
                                     (const float4*)d_in[6], (const float4*)d_in[8],
                                     (float4*)pwr);

    // fused QKV projection; q scale = dk^-0.5 * log2(e) (softmax in base-2)
    const float QSCALE = 0.125f * 1.4426950408889634f;
    gemm_mma<<<dim3(18, 256), 256, GEMM_SMEM>>>(
        pxr, pwr, bq, bk, bv, pq, pk, pv, QSCALE, 1);

    attn_mma<<<dim3(256, 12), 256, ATTN_SMEM>>>(
        pq, pk, pv, pmask, probs_ptr, pctx, probs_ptr != nullptr ? 1 : 0);

    // O projection: part 0 only, grid (6, 256)
    if (do_out)
        gemm_mma<<<dim3(6, 256), 256, GEMM_SMEM>>>(
            pctx, pwr + 3 * 589824, bo, bo, bo, out_ptr, out_ptr, out_ptr, 1.0f, 0);
}

// round 8
// speedup vs baseline: 2.2681x; 1.1523x over previous
#include <cuda_runtime.h>
#include <cuda_fp16.h>
#include <cstdint>

#define OUT_ELEMS   25165824L   // 128*256*768
#define PROBS_ELEMS 50331648L   // 12*256*128*128

// Scratch (allocation-free rule: device globals). Reinterpreted as half where noted.
__device__ float g_q[12582912];     // half[25165824]
__device__ float g_k[12582912];     // half[25165824]
__device__ float g_v[12582912];     // half[25165824]
__device__ float g_ctx[12582912];   // half[25165824]
__device__ float g_xh[12582912];    // half[25165824]  x in fp16
__device__ float g_wh[1179648];     // half[4][589824] weights in fp16

// ---------------------------------------------------------------------------
// Helpers
// ---------------------------------------------------------------------------
__device__ __forceinline__ uint32_t smem_u32(const void* p) {
    uint32_t a;
    asm("{ .reg .u64 t; cvta.to.shared.u64 t, %1; cvt.u32.u64 %0, t; }" : "=r"(a) : "l"(p));
    return a;
}
__device__ __forceinline__ void cp16(uint32_t s, const void* g) {
    asm volatile("cp.async.cg.shared.global [%0], [%1], 16;"
        :: "r"(s), "l"((unsigned long long)__cvta_generic_to_global(g)) : "memory");
}
__device__ __forceinline__ void mma16816(float (&d)[4],
    uint32_t a0, uint32_t a1, uint32_t a2, uint32_t a3, uint32_t b0, uint32_t b1) {
    asm volatile(
        "mma.sync.aligned.m16n8k16.row.col.f32.f16.f16.f32 "
        "{%0,%1,%2,%3}, {%4,%5,%6,%7}, {%8,%9}, {%0,%1,%2,%3};"
        : "+f"(d[0]), "+f"(d[1]), "+f"(d[2]), "+f"(d[3])
        : "r"(a0), "r"(a1), "r"(a2), "r"(a3), "r"(b0), "r"(b1));
}
#define LDSM4(r0, r1, r2, r3, addr) \
    asm volatile("ldmatrix.sync.aligned.m8n8.x4.shared.b16 {%0,%1,%2,%3}, [%4];" \
        : "=r"(r0), "=r"(r1), "=r"(r2), "=r"(r3) : "r"(addr))

// ---------------------------------------------------------------------------
// fp16 mma.sync NT-GEMM (f32 accum), 3-stage cp.async, ldmatrix.
// A [M,768] half; B fused [nparts*768, 768] half; BM=BN=128, BK=64, NT=12.
// Warp grid 4m x 2n, warp tile 32x64. LDH=72 halves (144B rows, conflict-free).
// ---------------------------------------------------------------------------
#define NS 3
#define LDH      72
#define A_HALFS  (128 * LDH)            // 9216 halves
#define STAGE_H  (2 * A_HALFS)          // 18432 halves (A+B)
#define GEMM_SMEM (NS * STAGE_H * 2)    // 110592 bytes
#define NT 12                           // 768/64

__device__ __forceinline__ void load_stage(
    __half* stg, const __half* Ab, const __half* Bb, int k0, int tid)
{
#pragma unroll
    for (int i = 0; i < 4; i++) {
        int q  = tid + i * 256;     // 0..1023
        int r  = q >> 3;            // row 0..127
        int cc = q & 7;             // 16B chunk (8 halves)
        cp16(smem_u32(stg + r * LDH + cc * 8),            Ab + (long)r * 768 + k0 + cc * 8);
        cp16(smem_u32(stg + A_HALFS + r * LDH + cc * 8),  Bb + (long)r * 768 + k0 + cc * 8);
    }
    asm volatile("cp.async.commit_group;" ::: "memory");
}

__global__ __launch_bounds__(256, 2) void gemm_mma(
    const __half* __restrict__ A, const __half* __restrict__ B,
    const float* __restrict__ bias0, const float* __restrict__ bias1,
    const float* __restrict__ bias2,
    void* __restrict__ C0, void* __restrict__ C1, void* __restrict__ C2,
    float s0, int out_half)
{
    extern __shared__ __half smh[];

    const int tid  = threadIdx.x;
    const int wid  = tid >> 5;
    const int lane = tid & 31;
    const int g    = lane >> 2;
    const int tg   = lane & 3;
    const int lr   = lane & 7;
    const int lq   = lane >> 3;
    const int wm   = wid >> 1;
    const int wn   = wid & 1;
    const long bm  = (long)blockIdx.y * 128;
    const int part = blockIdx.x / 6;
    const int bn   = (blockIdx.x % 6) * 128;

    const float* bias = (part == 0) ? bias0 : (part == 1) ? bias1 : bias2;
    void* C           = (part == 0) ? C0    : (part == 1) ? C1    : C2;
    const float scale = (part == 0) ? s0 : 1.0f;

    const __half* Ab = A + bm * 768;
    const __half* Bb = B + (long)blockIdx.x * 128 * 768;

    float acc[2][8][4];
#pragma unroll
    for (int mf = 0; mf < 2; mf++)
#pragma unroll
        for (int nf = 0; nf < 8; nf++)
#pragma unroll
            for (int r = 0; r < 4; r++) acc[mf][nf][r] = 0.0f;

    load_stage(smh,           Ab, Bb, 0,  tid);
    load_stage(smh + STAGE_H, Ab, Bb, 64, tid);

    const uint32_t smb = smem_u32(smh);
    // ldmatrix byte offsets within a stage (x4: matrices m0/m0+8 at k0, then k0+8)
    const uint32_t aoffA = ((wm * 32 + (lq & 1) * 8 + lr) * LDH + (lq >> 1) * 8) * 2;
    const uint32_t aoffB = (uint32_t)(A_HALFS * 2) +
                           ((wn * 64 + (lq >> 1) * 8 + lr) * LDH + (lq & 1) * 8) * 2;

    int s = 0;
    for (int kt = 0; kt < NT; kt++) {
        if (kt < NT - 1) asm volatile("cp.async.wait_group 1;" ::: "memory");
        else             asm volatile("cp.async.wait_group 0;" ::: "memory");
        __syncthreads();

        if (kt + 2 < NT) {
            int sn = (s + 2 >= NS) ? s + 2 - NS : s + 2;
            load_stage(smh + sn * STAGE_H, Ab, Bb, (kt + 2) * 64, tid);
        }

        const uint32_t sb  = smb + (uint32_t)(s * STAGE_H * 2);
        const uint32_t aA0 = sb + aoffA;
        const uint32_t aA1 = aA0 + 16 * LDH * 2;
        const uint32_t aB  = sb + aoffB;

#pragma unroll
        for (int t = 0; t < 4; t++) {
            const uint32_t ko = t * 32;             // 16 halves per k-step
            uint32_t a0[4], a1[4], b[4][4];
            LDSM4(a0[0], a0[1], a0[2], a0[3], aA0 + ko);
            LDSM4(a1[0], a1[1], a1[2], a1[3], aA1 + ko);
            LDSM4(b[0][0], b[0][1], b[0][2], b[0][3], aB + 0 * (16 * LDH * 2) + ko);
            LDSM4(b[1][0], b[1][1], b[1][2], b[1][3], aB + 1 * (16 * LDH * 2) + ko);
            LDSM4(b[2][0], b[2][1], b[2][2], b[2][3], aB + 2 * (16 * LDH * 2) + ko);
            LDSM4(b[3][0], b[3][1], b[3][2], b[3][3], aB + 3 * (16 * LDH * 2) + ko);
#pragma unroll
            for (int pr = 0; pr < 4; pr++) {
                mma16816(acc[0][2 * pr],     a0[0], a0[1], a0[2], a0[3], b[pr][0], b[pr][1]);
                mma16816(acc[1][2 * pr],     a1[0], a1[1], a1[2], a1[3], b[pr][0], b[pr][1]);
                mma16816(acc[0][2 * pr + 1], a0[0], a0[1], a0[2], a0[3], b[pr][2], b[pr][3]);
                mma16816(acc[1][2 * pr + 1], a1[0], a1[1], a1[2], a1[3], b[pr][2], b[pr][3]);
            }
        }
        if (++s == NS) s = 0;
    }

    // -------- epilogue --------
#pragma unroll
    for (int mf = 0; mf < 2; mf++) {
        long row0 = bm + wm * 32 + mf * 16 + g;
#pragma unroll
        for (int nf = 0; nf < 8; nf++) {
            int col = bn + wn * 64 + nf * 8 + tg * 2;
            float b0 = bias[col], b1 = bias[col + 1];
            float v0 = (acc[mf][nf][0] + b0) * scale;
            float v1 = (acc[mf][nf][1] + b1) * scale;
            float v2 = (acc[mf][nf][2] + b0) * scale;
            float v3 = (acc[mf][nf][3] + b1) * scale;
            if (out_half) {
                __half* Ch = (__half*)C;
                *reinterpret_cast<__half2*>(Ch + row0 * 768 + col) =
                    __floats2half2_rn(v0, v1);
                *reinterpret_cast<__half2*>(Ch + (row0 + 8) * 768 + col) =
                    __floats2half2_rn(v2, v3);
            } else {
                float* Cf = (float*)C;
                *reinterpret_cast<float2*>(Cf + row0 * 768 + col)       = make_float2(v0, v1);
                *reinterpret_cast<float2*>(Cf + (row0 + 8) * 768 + col) = make_float2(v2, v3);
            }
        }
    }
}

// ---------------------------------------------------------------------------
// fp32 -> fp16 conversion passes
// ---------------------------------------------------------------------------
__global__ void half_x_k(const float4* __restrict__ in, __half2* __restrict__ out, int n4)
{
    int i = blockIdx.x * blockDim.x + threadIdx.x;
    if (i < n4) {
        float4 v = in[i];
        out[i * 2]     = __floats2half2_rn(v.x, v.y);
        out[i * 2 + 1] = __floats2half2_rn(v.z, v.w);
    }
}

__global__ void half_w_k(const float4* __restrict__ w0, const float4* __restrict__ w1,
                         const float4* __restrict__ w2, const float4* __restrict__ w3,
                         __half2* __restrict__ o)
{
    const float4* in = (blockIdx.y == 0) ? w0 : (blockIdx.y == 1) ? w1 :
                       (blockIdx.y == 2) ? w2 : w3;
    __half2* out = o + (size_t)blockIdx.y * 294912;   // 589824 halves / 2
    int i = blockIdx.x * blockDim.x + threadIdx.x;    // 147456 float4s
    float4 v = in[i];
    out[i * 2]     = __floats2half2_rn(v.x, v.y);
    out[i * 2 + 1] = __floats2half2_rn(v.z, v.w);
}

// ---------------------------------------------------------------------------
// Attention per (h, c): fp16 mma m16n8k16 + ldmatrix; softmax via h2exp2.
// q pre-scaled by dk^-0.5 * log2(e) (log2-domain softmax).
// ---------------------------------------------------------------------------
#define QK_LDH  72      // 64 halves + pad; 144B rows
#define PS_LDH  136     // 128 halves + pad; 272B rows
#define VT_LDH  136
// qs+ks = 2*128*72 = 18432 halves; ps overlay = 128*136 = 17408 <= 18432
// vt = 64*136 = 8704 halves
#define ATTN_SMEM ((2 * 128 * QK_LDH + 64 * VT_LDH) * 2)   // 54272 B

__global__ __launch_bounds__(256, 2) void attn_mma(
    const __half* __restrict__ q, const __half* __restrict__ k, const __half* __restrict__ v,
    const unsigned char* __restrict__ mask,
    float* __restrict__ probs, __half* __restrict__ ctx, int write_probs)
{
    extern __shared__ __half smh[];
    __half* qs = smh;
    __half* ks = smh + 128 * QK_LDH;
    __half* ps = smh;                        // overlays qs/ks after phase 1
    __half* vt = smh + 2 * 128 * QK_LDH;
    __shared__ unsigned char mask_s[128];

    const int c   = blockIdx.x;
    const int h   = blockIdx.y;
    const int tid = threadIdx.x;
    const int w    = tid >> 5;
    const int lane = tid & 31;
    const int g    = lane >> 2;
    const int tg   = lane & 3;
    const int lr   = lane & 7;
    const int lq   = lane >> 3;

    // ---- load Q,K rows (64 halves = 4x16B); V transposed; mask ----
#pragma unroll
    for (int l = 0; l < 4; l++) {
        int idx = tid + l * 256;             // 1024 16B-chunks per tensor
        int i  = idx >> 3;
        int d8 = (idx & 7) * 8;
        size_t go = ((size_t)i * 256 + c) * 768 + h * 64 + d8;
        *reinterpret_cast<uint4*>(&qs[i * QK_LDH + d8]) =
            *reinterpret_cast<const uint4*>(q + go);
        *reinterpret_cast<uint4*>(&ks[i * QK_LDH + d8]) =
            *reinterpret_cast<const uint4*>(k + go);
    }
#pragma unroll
    for (int l = 0; l < 32; l++) {
        int idx = tid + l * 256;             // 8192 scalars
        int d = idx & 63;
        int j = idx >> 6;
        vt[d * VT_LDH + j] = v[((size_t)j * 256 + c) * 768 + h * 64 + d];
    }
    if (tid < 128) mask_s[tid] = mask[(size_t)tid * 256 + c];
    __syncthreads();

    // ---- phase 1: S' = Q' K^T (log2 domain), warp tile 16x128, k=64 ----
    float acc[16][4];
#pragma unroll
    for (int nf = 0; nf < 16; nf++)
#pragma unroll
        for (int r = 0; r < 4; r++) acc[nf][r] = 0.0f;

    const uint32_t qsb = smem_u32(qs);
    const uint32_t ksb = smem_u32(ks);
    const uint32_t aQ = qsb + ((w * 16 + (lq & 1) * 8 + lr) * QK_LDH + (lq >> 1) * 8) * 2;
    const uint32_t aK = ksb + (((lq >> 1) * 8 + lr) * QK_LDH + (lq & 1) * 8) * 2;

#pragma unroll
    for (int t = 0; t < 4; t++) {
        const uint32_t ko = t * 32;          // 16 halves per k-step
        uint32_t a0[4];
        LDSM4(a0[0], a0[1], a0[2], a0[3], aQ + ko);
#pragma unroll
        for (int pr = 0; pr < 8; pr++) {
            uint32_t b0, b1, b2, b3;
            LDSM4(b0, b1, b2, b3, aK + pr * (16 * QK_LDH * 2) + ko);
            mma16816(acc[2 * pr],     a0[0], a0[1], a0[2], a0[3], b0, b1);
            mma16816(acc[2 * pr + 1], a0[0], a0[1], a0[2], a0[3], b2, b3);
        }
    }

    // ---- mask ----
#pragma unroll
    for (int nf = 0; nf < 16; nf++) {
        int j = nf * 8 + tg * 2;
        if (mask_s[j])     { acc[nf][0] = -14000.0f; acc[nf][2] = -14000.0f; }
        if (mask_s[j + 1]) { acc[nf][1] = -14000.0f; acc[nf][3] = -14000.0f; }
    }

    // ---- softmax (log2 domain), exp2 in fp16x2 ----
    float m0 = -1e30f, m1 = -1e30f;
#pragma unroll
    for (int nf = 0; nf < 16; nf++) {
        m0 = fmaxf(m0, fmaxf(acc[nf][0], acc[nf][1]));
        m1 = fmaxf(m1, fmaxf(acc[nf][2], acc[nf][3]));
    }
    m0 = fmaxf(m0, __shfl_xor_sync(0xffffffffu, m0, 1));
    m0 = fmaxf(m0, __shfl_xor_sync(0xffffffffu, m0, 2));
    m1 = fmaxf(m1, __shfl_xor_sync(0xffffffffu, m1, 1));
    m1 = fmaxf(m1, __shfl_xor_sync(0xffffffffu, m1, 2));
    float s0 = 0.0f, s1 = 0.0f;
#pragma unroll
    for (int nf = 0; nf < 16; nf++) {
        half2 h01 = __floats2half2_rn(acc[nf][0] - m0, acc[nf][1] - m0);
        half2 h23 = __floats2half2_rn(acc[nf][2] - m1, acc[nf][3] - m1);
        h01 = h2exp2(h01);
        h23 = h2exp2(h23);
        float2 e01 = __half22float2(h01);
        float2 e23 = __half22float2(h23);
        acc[nf][0] = e01.x; acc[nf][1] = e01.y;
        acc[nf][2] = e23.x; acc[nf][3] = e23.y;
        s0 += e01.x + e01.y;
        s1 += e23.x + e23.y;
    }
    s0 += __shfl_xor_sync(0xffffffffu, s0, 1);
    s0 += __shfl_xor_sync(0xffffffffu, s0, 2);
    s1 += __shfl_xor_sync(0xffffffffu, s1, 1);
    s1 += __shfl_xor_sync(0xffffffffu, s1, 2);
    float i0 = 1.0f / s0, i1 = 1.0f / s1;
#pragma unroll
    for (int nf = 0; nf < 16; nf++) {
        acc[nf][0] *= i0; acc[nf][1] *= i0;
        acc[nf][2] *= i1; acc[nf][3] *= i1;
    }

    __syncthreads();   // all warps done reading qs/ks

    // ---- P -> smem (fp16); probs -> gmem (fp32) ----
    const int row0 = w * 16 + g;
    if (write_probs) {
        float* pb = probs + ((size_t)h * 256 + c) * 16384;
#pragma unroll
        for (int nf = 0; nf < 16; nf++) {
            int col = nf * 8 + tg * 2;
            *reinterpret_cast<float2*>(pb + row0 * 128 + col) =
                make_float2(acc[nf][0], acc[nf][1]);
            *reinterpret_cast<float2*>(pb + (row0 + 8) * 128 + col) =
                make_float2(acc[nf][2], acc[nf][3]);
        }
    }
#pragma unroll
    for (int nf = 0; nf < 16; nf++) {
        int col = nf * 8 + tg * 2;
        *reinterpret_cast<__half2*>(&ps[row0 * PS_LDH + col]) =
            __floats2half2_rn(acc[nf][0], acc[nf][1]);
        *reinterpret_cast<__half2*>(&ps[(row0 + 8) * PS_LDH + col]) =
            __floats2half2_rn(acc[nf][2], acc[nf][3]);
    }
    __syncthreads();

    // ---- phase 2: ctx = P V, warp tile 16x64, k=128 ----
    float acc2[8][4];
#pragma unroll
    for (int nf = 0; nf < 8; nf++)
#pragma unroll
        for (int r = 0; r < 4; r++) acc2[nf][r] = 0.0f;

    const uint32_t psb = smem_u32(ps);
    const uint32_t vtb = smem_u32(vt);
    const uint32_t aP = psb + ((w * 16 + (lq & 1) * 8 + lr) * PS_LDH + (lq >> 1) * 8) * 2;
    const uint32_t aV = vtb + (((lq >> 1) * 8 + lr) * VT_LDH + (lq & 1) * 8) * 2;

#pragma unroll
    for (int t = 0; t < 8; t++) {
        const uint32_t ko = t * 32;          // 16 halves per k-step
        uint32_t a0[4];
        LDSM4(a0[0], a0[1], a0[2], a0[3], aP + ko);
#pragma unroll
        for (int pr = 0; pr < 4; pr++) {
            uint32_t b0, b1, b2, b3;
            LDSM4(b0, b1, b2, b3, aV + pr * (16 * VT_LDH * 2) + ko);
            mma16816(acc2[2 * pr],     a0[0], a0[1], a0[2], a0[3], b0, b1);
            mma16816(acc2[2 * pr + 1], a0[0], a0[1], a0[2], a0[3], b2, b3);
        }
    }

    // ---- ctx epilogue (fp16: feeds O projection A operand) ----
#pragma unroll
    for (int nf = 0; nf < 8; nf++) {
        int d = nf * 8 + tg * 2;
        size_t go0 = ((size_t)row0 * 256 + c) * 768 + h * 64 + d;
        size_t go1 = ((size_t)(row0 + 8) * 256 + c) * 768 + h * 64 + d;
        *reinterpret_cast<__half2*>(ctx + go0) = __floats2half2_rn(acc2[nf][0], acc2[nf][1]);
        *reinterpret_cast<__half2*>(ctx + go1) = __floats2half2_rn(acc2[nf][2], acc2[nf][3]);
    }
}

// ---------------------------------------------------------------------------
extern "C" void kernel_launch(void* const* d_in, const int* in_sizes, int n_in,
                              void* d_out, int out_size)
{
    const float*         x     = (const float*)d_in[0];
    const unsigned char* pmask = (const unsigned char*)d_in[1];
    const float* bq = (const float*)d_in[3];
    const float* bk = (const float*)d_in[5];
    const float* bv = (const float*)d_in[7];
    const float* bo = (const float*)d_in[9];

    void *pq_, *pk_, *pv_, *pctx_, *pxh_, *pwh_;
    cudaGetSymbolAddress(&pq_,   g_q);
    cudaGetSymbolAddress(&pk_,   g_k);
    cudaGetSymbolAddress(&pv_,   g_v);
    cudaGetSymbolAddress(&pctx_, g_ctx);
    cudaGetSymbolAddress(&pxh_,  g_xh);
    cudaGetSymbolAddress(&pwh_,  g_wh);
    __half* pq   = (__half*)pq_;
    __half* pk   = (__half*)pk_;
    __half* pv   = (__half*)pv_;
    __half* pctx = (__half*)pctx_;
    __half* pxh  = (__half*)pxh_;
    __half* pwh  = (__half*)pwh_;

    float* out = (float*)d_out;
    float* out_ptr   = out;
    float* probs_ptr = nullptr;
    int    do_out    = 1;
    long   os        = (long)out_size;
    if (os >= OUT_ELEMS + PROBS_ELEMS) {
        probs_ptr = out + OUT_ELEMS;
    } else if (os == PROBS_ELEMS) {
        probs_ptr = out;
        do_out = 0;
    }

    cudaFuncSetAttribute(gemm_mma, cudaFuncAttributeMaxDynamicSharedMemorySize, GEMM_SMEM);
    cudaFuncSetAttribute(attn_mma, cudaFuncAttributeMaxDynamicSharedMemorySize, ATTN_SMEM);

    // fp32 -> fp16 conversion of GEMM inputs
    half_x_k<<<24576, 256>>>((const float4*)x, (__half2*)pxh, 6291456);
    half_w_k<<<dim3(576, 4), 256>>>((const float4*)d_in[2], (const float4*)d_in[4],
                                    (const float4*)d_in[6], (const float4*)d_in[8],
                                    (__half2*)pwh);

    // fused QKV projection; q scale = dk^-0.5 * log2(e) (softmax in base-2)
    const float QSCALE = 0.125f * 1.4426950408889634f;
    gemm_mma<<<dim3(18, 256), 256, GEMM_SMEM>>>(
        pxh, pwh, bq, bk, bv, pq, pk, pv, QSCALE, 1);

    attn_mma<<<dim3(256, 12), 256, ATTN_SMEM>>>(
        pq, pk, pv, pmask, probs_ptr, pctx, probs_ptr != nullptr ? 1 : 0);

    // O projection: fp32 output
    if (do_out)
        gemm_mma<<<dim3(6, 256), 256, GEMM_SMEM>>>(
            pctx, pwh + 3 * 589824, bo, bo, bo, out_ptr, out_ptr, out_ptr, 1.0f, 0);
}